// round 1
// baseline (speedup 1.0000x reference)
#include <cuda_runtime.h>

#define TW 8
#define C_ 64
#define D_ 32
#define S_ 32
#define H_ 64
#define W_ 64
#define B_ 4
#define HW_ (H_*W_)       /* 4096  */
#define DHW_ (D_*HW_)     /* 131072 */
#define XROW 33           /* x-tile row stride (floats), conflict-free lane-d */
#define KROW 36           /* kT/vS row stride: 16B-aligned float4, mild write conflicts */

/* shared memory layout (float offsets) */
#define OFF_XS   0
#define N_XS     (C_*TW*XROW)            /* 16896 */
#define OFF_WK   (OFF_XS + N_XS)
#define OFF_WQ   (OFF_WK + S_*C_)
#define OFF_WV   (OFF_WQ + S_*C_)
#define OFF_WO   (OFF_WV + S_*C_)        /* [c][s] */
#define OFF_BK   (OFF_WO + C_*S_)
#define OFF_BQ   (OFF_BK + S_)
#define OFF_BV   (OFF_BQ + S_)
#define OFF_BO   (OFF_BV + S_)
#define OFF_KT   (OFF_BO + C_)
#define N_PW     (2*S_*KROW)             /* kT + vS per warp = 2304 */
#define SMEM_FLOATS (OFF_KT + 8*N_PW)    /* 43680 floats = 174720 B */

__global__ void __launch_bounds__(256, 1)
attn_fused_kernel(const float* __restrict__ x,
                  const float* __restrict__ Wk, const float* __restrict__ bk,
                  const float* __restrict__ Wq, const float* __restrict__ bq,
                  const float* __restrict__ Wv, const float* __restrict__ bv,
                  const float* __restrict__ Wo, const float* __restrict__ bo,
                  float* __restrict__ out)
{
    extern __shared__ float sm[];
    const int tid = threadIdx.x;
    const int bx  = blockIdx.x;
    const int wt  = bx & 7;           /* which 8-wide w tile   */
    const int h   = (bx >> 3) & 63;
    const int b   = bx >> 9;
    const int w0  = wt * TW;

    /* ---- load weights/biases into smem ---- */
    for (int i = tid; i < S_*C_; i += 256) {
        sm[OFF_WK + i] = Wk[i];
        sm[OFF_WQ + i] = Wq[i];
        sm[OFF_WV + i] = Wv[i];
        sm[OFF_WO + i] = Wo[i];       /* Wo is (C,S) row-major = [c][s] */
    }
    if (tid < S_) {
        sm[OFF_BK + tid] = bk[tid];
        sm[OFF_BQ + tid] = bq[tid];
        sm[OFF_BV + tid] = bv[tid];
    }
    if (tid < C_) sm[OFF_BO + tid] = bo[tid];

    /* ---- stage x tile: [c][w][d] rows padded to XROW ---- */
    const int xbase = b*C_*DHW_ + h*W_ + w0;
    for (int e = tid; e < C_*D_*TW; e += 256) {
        const int w = e & 7;
        const int d = (e >> 3) & 31;
        const int c = e >> 8;
        sm[OFF_XS + (c*TW + w)*XROW + d] = x[xbase + c*DHW_ + d*HW_ + w];
    }
    __syncthreads();

    const int warp = tid >> 5;        /* pixel within tile */
    const int lane = tid & 31;        /* d (and j) index   */

    float* kT = sm + OFF_KT + warp*N_PW;     /* kT[i][s], row stride KROW */
    float* vS = kT + S_*KROW;                /* vS[s][i], row stride KROW */
    const float* xs = sm + OFF_XS + warp*XROW;

    /* ---- projections: k,q,v[s] for this lane's d column ---- */
    float k[S_], q[S_], v[S_];
#pragma unroll
    for (int s = 0; s < S_; s++) {
        k[s] = sm[OFF_BK + s];
        q[s] = sm[OFF_BQ + s];
        v[s] = sm[OFF_BV + s];
    }

#pragma unroll 4
    for (int c0 = 0; c0 < C_; c0 += 4) {
        const float xv0 = xs[(c0+0)*(TW*XROW) + lane];
        const float xv1 = xs[(c0+1)*(TW*XROW) + lane];
        const float xv2 = xs[(c0+2)*(TW*XROW) + lane];
        const float xv3 = xs[(c0+3)*(TW*XROW) + lane];
#pragma unroll
        for (int s = 0; s < S_; s++) {
            const float4 wk4 = *(const float4*)&sm[OFF_WK + s*C_ + c0];
            k[s] = fmaf(wk4.x, xv0, fmaf(wk4.y, xv1, fmaf(wk4.z, xv2, fmaf(wk4.w, xv3, k[s]))));
            const float4 wq4 = *(const float4*)&sm[OFF_WQ + s*C_ + c0];
            q[s] = fmaf(wq4.x, xv0, fmaf(wq4.y, xv1, fmaf(wq4.z, xv2, fmaf(wq4.w, xv3, q[s]))));
            const float4 wv4 = *(const float4*)&sm[OFF_WV + s*C_ + c0];
            v[s] = fmaf(wv4.x, xv0, fmaf(wv4.y, xv1, fmaf(wv4.z, xv2, fmaf(wv4.w, xv3, v[s]))));
        }
    }

    /* stash k (transposed: kT[i=d][s]) and v (vS[s][i=d]) in smem */
#pragma unroll
    for (int s = 0; s < S_; s++) kT[lane*KROW + s] = k[s];
#pragma unroll
    for (int s = 0; s < S_; s++) vS[s*KROW + lane] = v[s];
    __syncwarp();

    /* ---- scores[i][j=lane] = (1/sqrt(S)) * sum_s k[s][i]*q[s][j] ---- */
    float a[D_];
#pragma unroll
    for (int i = 0; i < D_; i++) {
        float acc = 0.f;
#pragma unroll
        for (int s0 = 0; s0 < S_; s0 += 4) {
            const float4 kk = *(const float4*)&kT[i*KROW + s0];
            acc = fmaf(kk.x, q[s0+0], acc);
            acc = fmaf(kk.y, q[s0+1], acc);
            acc = fmaf(kk.z, q[s0+2], acc);
            acc = fmaf(kk.w, q[s0+3], acc);
        }
        a[i] = acc * 0.17677669529663687f;   /* 1/sqrt(32) */
    }

    /* ---- softmax over i (in-register, per lane/column j) ---- */
    float m = a[0];
#pragma unroll
    for (int i = 1; i < D_; i++) m = fmaxf(m, a[i]);
    float ssum = 0.f;
#pragma unroll
    for (int i = 0; i < D_; i++) { a[i] = __expf(a[i] - m); ssum += a[i]; }
    const float inv = 1.0f / ssum;
#pragma unroll
    for (int i = 0; i < D_; i++) a[i] *= inv;

    /* ---- o[s][j=lane] = sum_i v[s][i] * a[i] ---- */
    float o[S_];
#pragma unroll
    for (int s = 0; s < S_; s++) {
        float acc = 0.f;
#pragma unroll
        for (int i0 = 0; i0 < D_; i0 += 4) {
            const float4 vv = *(const float4*)&vS[s*KROW + i0];
            acc = fmaf(vv.x, a[i0+0], acc);
            acc = fmaf(vv.y, a[i0+1], acc);
            acc = fmaf(vv.z, a[i0+2], acc);
            acc = fmaf(vv.w, a[i0+3], acc);
        }
        o[s] = acc;
    }

    /* ---- out[c] = bo[c] + sum_s Wo[c][s] o[s] + x  (residual, in-place in xs) ---- */
#pragma unroll 4
    for (int c = 0; c < C_; c++) {
        float acc = sm[OFF_BO + c];
#pragma unroll
        for (int s0 = 0; s0 < S_; s0 += 4) {
            const float4 ww = *(const float4*)&sm[OFF_WO + c*S_ + s0];
            acc = fmaf(ww.x, o[s0+0], acc);
            acc = fmaf(ww.y, o[s0+1], acc);
            acc = fmaf(ww.z, o[s0+2], acc);
            acc = fmaf(ww.w, o[s0+3], acc);
        }
        sm[OFF_XS + (c*TW + warp)*XROW + lane] += acc;
    }
    __syncthreads();

    /* ---- coalesced store of result tile ---- */
    for (int e = tid; e < C_*D_*TW; e += 256) {
        const int w = e & 7;
        const int d = (e >> 3) & 31;
        const int c = e >> 8;
        out[xbase + c*DHW_ + d*HW_ + w] = sm[OFF_XS + (c*TW + w)*XROW + d];
    }
}

extern "C" void kernel_launch(void* const* d_in, const int* in_sizes, int n_in,
                              void* d_out, int out_size)
{
    const float* x  = (const float*)d_in[0];
    const float* Wk = (const float*)d_in[1];
    const float* bk = (const float*)d_in[2];
    const float* Wq = (const float*)d_in[3];
    const float* bq = (const float*)d_in[4];
    const float* Wv = (const float*)d_in[5];
    const float* bv = (const float*)d_in[6];
    const float* Wo = (const float*)d_in[7];
    const float* bo = (const float*)d_in[8];
    float* out = (float*)d_out;

    const size_t smem_bytes = (size_t)SMEM_FLOATS * sizeof(float);
    cudaFuncSetAttribute(attn_fused_kernel,
                         cudaFuncAttributeMaxDynamicSharedMemorySize,
                         (int)smem_bytes);

    const int grid = B_ * H_ * (W_ / TW);   /* 2048 blocks */
    attn_fused_kernel<<<grid, 256, smem_bytes>>>(x, Wk, bk, Wq, bq, Wv, bv, Wo, bo, out);
}

// round 2
// speedup vs baseline: 1.4738x; 1.4738x over previous
#include <cuda_runtime.h>

typedef unsigned long long ull;

#define TW 8
#define C_ 64
#define D_ 32
#define S_ 32
#define SP_ 16            /* s-pairs */
#define H_ 64
#define W_ 64
#define B_ 4
#define HW_ (H_*W_)       /* 4096  */
#define DHW_ (D_*HW_)     /* 131072 */

#define XROW 68           /* x row stride (floats): [w][d][c-contig] */
#define PIXSTRIDE 2180    /* per-pixel x region: 32*68 + 4 pad (mod 32 = 4) */

/* shared memory layout (float offsets) */
#define OFF_XS   0
#define N_XS     (TW*PIXSTRIDE)          /* 17440 */
#define OFF_WKT  (OFF_XS + N_XS)         /* WkT [c][s] */
#define OFF_WQT  (OFF_WKT + C_*S_)
#define OFF_WVT  (OFF_WQT + C_*S_)
#define OFF_WO   (OFF_WVT + C_*S_)       /* Wo  [c][s] (native) */
#define OFF_BK   (OFF_WO + C_*S_)
#define OFF_BQ   (OFF_BK + S_)
#define OFF_BV   (OFF_BQ + S_)
#define OFF_BO   (OFF_BV + S_)
#define OFF_SC   (OFF_BO + C_)           /* per-warp scratch */
#define KT_ROW   36                      /* kT[i][s] row stride */
#define VS_ROW   72                      /* vS[sp][i] (float2 per i) row stride */
#define N_PW     (D_*KT_ROW + SP_*VS_ROW)  /* 1152+1152 = 2304 */
#define SMEM_FLOATS (OFF_SC + 8*N_PW)    /* 44224 floats = 176896 B */

__device__ __forceinline__ ull f2fma(ull a, ull b, ull c) {
    ull d; asm("fma.rn.f32x2 %0,%1,%2,%3;" : "=l"(d) : "l"(a), "l"(b), "l"(c)); return d;
}
__device__ __forceinline__ ull f2add(ull a, ull b) {
    ull d; asm("add.rn.f32x2 %0,%1,%2;" : "=l"(d) : "l"(a), "l"(b)); return d;
}
__device__ __forceinline__ ull f2dup(float x) {
    ull d; asm("mov.b64 %0,{%1,%1};" : "=l"(d) : "f"(x)); return d;
}
__device__ __forceinline__ float2 f2unpack(ull a) {
    float lo, hi; asm("mov.b64 {%0,%1},%2;" : "=f"(lo), "=f"(hi) : "l"(a));
    return make_float2(lo, hi);
}

__global__ void __launch_bounds__(256, 1)
attn_fused_kernel(const float* __restrict__ x,
                  const float* __restrict__ Wk, const float* __restrict__ bk,
                  const float* __restrict__ Wq, const float* __restrict__ bq,
                  const float* __restrict__ Wv, const float* __restrict__ bv,
                  const float* __restrict__ Wo, const float* __restrict__ bo,
                  float* __restrict__ out)
{
    extern __shared__ float sm[];
    const int tid = threadIdx.x;
    const int bx  = blockIdx.x;
    const int wt  = bx & 7;
    const int h   = (bx >> 3) & 63;
    const int b   = bx >> 9;
    const int w0  = wt * TW;

    /* ---- stage weights: k/q/v transposed to [c][s]; Wo native [c][s] ---- */
    for (int i = tid; i < C_*S_; i += 256) {
        const int s = i & 31;
        const int c = i >> 5;
        sm[OFF_WKT + i] = Wk[s*C_ + c];
        sm[OFF_WQT + i] = Wq[s*C_ + c];
        sm[OFF_WVT + i] = Wv[s*C_ + c];
        sm[OFF_WO  + i] = Wo[i];
    }
    if (tid < S_) {
        sm[OFF_BK + tid] = bk[tid];
        sm[OFF_BQ + tid] = bq[tid];
        sm[OFF_BV + tid] = bv[tid];
    }
    if (tid < C_) sm[OFF_BO + tid] = bo[tid];

    /* ---- stage x tile: [w][d][c-contig] ---- */
    const int xbase = b*C_*DHW_ + h*W_ + w0;
    for (int e = tid; e < C_*D_*TW; e += 256) {
        const int w = e & 7;
        const int d = (e >> 3) & 31;
        const int c = e >> 8;
        sm[OFF_XS + w*PIXSTRIDE + d*XROW + c] = x[xbase + c*DHW_ + d*HW_ + w];
    }
    __syncthreads();

    const int warp = tid >> 5;        /* pixel within tile */
    const int lane = tid & 31;        /* d (and j) index   */

    float* xr = sm + OFF_XS + warp*PIXSTRIDE + lane*XROW;   /* this thread's x row (c contig) */
    float* kT = sm + OFF_SC + warp*N_PW;                    /* kT[i][s], stride KT_ROW */
    float* vS = kT + D_*KT_ROW;                             /* vS[sp][i] float2, stride VS_ROW */

    /* ---- projections (s-pair packed) ---- */
    ull k2[SP_], q2[SP_], v2[SP_];
#pragma unroll
    for (int sp = 0; sp < SP_; sp++) {
        k2[sp] = *(const ull*)&sm[OFF_BK + 2*sp];
        q2[sp] = *(const ull*)&sm[OFF_BQ + 2*sp];
        v2[sp] = *(const ull*)&sm[OFF_BV + 2*sp];
    }

#pragma unroll 2
    for (int c0 = 0; c0 < C_; c0 += 4) {
        const float4 xq = *(const float4*)&xr[c0];
        ull xd[4];
        xd[0] = f2dup(xq.x); xd[1] = f2dup(xq.y);
        xd[2] = f2dup(xq.z); xd[3] = f2dup(xq.w);
#pragma unroll
        for (int cc = 0; cc < 4; cc++) {
            const int wb = (c0 + cc) * S_;
#pragma unroll
            for (int g = 0; g < 8; g++) {
                const ulonglong2 wk = *(const ulonglong2*)&sm[OFF_WKT + wb + 4*g];
                k2[2*g]   = f2fma(wk.x, xd[cc], k2[2*g]);
                k2[2*g+1] = f2fma(wk.y, xd[cc], k2[2*g+1]);
                const ulonglong2 wq = *(const ulonglong2*)&sm[OFF_WQT + wb + 4*g];
                q2[2*g]   = f2fma(wq.x, xd[cc], q2[2*g]);
                q2[2*g+1] = f2fma(wq.y, xd[cc], q2[2*g+1]);
                const ulonglong2 wv = *(const ulonglong2*)&sm[OFF_WVT + wb + 4*g];
                v2[2*g]   = f2fma(wv.x, xd[cc], v2[2*g]);
                v2[2*g+1] = f2fma(wv.y, xd[cc], v2[2*g+1]);
            }
        }
    }

    /* stash k (kT[i=lane][s], linear s) and v (vS[sp][i=lane] packed) */
#pragma unroll
    for (int sp = 0; sp < SP_; sp++) *(ull*)&kT[lane*KT_ROW + 2*sp] = k2[sp];
#pragma unroll
    for (int sp = 0; sp < SP_; sp++) *(ull*)&vS[sp*VS_ROW + 2*lane] = v2[sp];
    __syncwarp();

    /* ---- scores[i][j=lane] ---- */
    float a[D_];
#pragma unroll
    for (int i = 0; i < D_; i++) {
        ull acc0 = 0ULL, acc1 = 0ULL;
#pragma unroll
        for (int t = 0; t < 8; t++) {
            const ulonglong2 kk = *(const ulonglong2*)&kT[i*KT_ROW + 4*t];
            acc0 = f2fma(kk.x, q2[2*t],   acc0);
            acc1 = f2fma(kk.y, q2[2*t+1], acc1);
        }
        const float2 p = f2unpack(f2add(acc0, acc1));
        a[i] = (p.x + p.y) * 0.17677669529663687f;   /* 1/sqrt(32) */
    }

    /* ---- softmax over i (per lane/column j) ---- */
    float m = a[0];
#pragma unroll
    for (int i = 1; i < D_; i++) m = fmaxf(m, a[i]);
    float ssum = 0.f;
#pragma unroll
    for (int i = 0; i < D_; i++) { a[i] = __expf(a[i] - m); ssum += a[i]; }
    const float inv = 1.0f / ssum;

    /* dup normalized a[i] into packed regs */
    ull ad[D_];
#pragma unroll
    for (int i = 0; i < D_; i++) ad[i] = f2dup(a[i] * inv);

    /* ---- o[sp][j=lane] = sum_i vS[sp][i] * a[i] (s-pair packed) ---- */
    ull o2[SP_];
#pragma unroll
    for (int sp = 0; sp < SP_; sp++) {
        ull acc0 = 0ULL, acc1 = 0ULL;
#pragma unroll
        for (int t = 0; t < 16; t++) {
            const ulonglong2 vv = *(const ulonglong2*)&vS[sp*VS_ROW + 4*t];
            acc0 = f2fma(vv.x, ad[2*t],   acc0);
            acc1 = f2fma(vv.y, ad[2*t+1], acc1);
        }
        o2[sp] = f2add(acc0, acc1);
    }

    /* ---- out[c] = bo[c] + Wo[c][:]·o + x, written back into x row ---- */
#pragma unroll 4
    for (int c = 0; c < C_; c++) {
        ull acc0 = 0ULL, acc1 = 0ULL;
        const int wb = OFF_WO + c*S_;
#pragma unroll
        for (int t = 0; t < 8; t++) {
            const ulonglong2 ww = *(const ulonglong2*)&sm[wb + 4*t];
            acc0 = f2fma(ww.x, o2[2*t],   acc0);
            acc1 = f2fma(ww.y, o2[2*t+1], acc1);
        }
        const float2 p = f2unpack(f2add(acc0, acc1));
        xr[c] += p.x + p.y + sm[OFF_BO + c];
    }
    __syncthreads();

    /* ---- coalesced store ---- */
    for (int e = tid; e < C_*D_*TW; e += 256) {
        const int w = e & 7;
        const int d = (e >> 3) & 31;
        const int c = e >> 8;
        out[xbase + c*DHW_ + d*HW_ + w] = sm[OFF_XS + w*PIXSTRIDE + d*XROW + c];
    }
}

extern "C" void kernel_launch(void* const* d_in, const int* in_sizes, int n_in,
                              void* d_out, int out_size)
{
    const float* x  = (const float*)d_in[0];
    const float* Wk = (const float*)d_in[1];
    const float* bk = (const float*)d_in[2];
    const float* Wq = (const float*)d_in[3];
    const float* bq = (const float*)d_in[4];
    const float* Wv = (const float*)d_in[5];
    const float* bv = (const float*)d_in[6];
    const float* Wo = (const float*)d_in[7];
    const float* bo = (const float*)d_in[8];
    float* out = (float*)d_out;

    const size_t smem_bytes = (size_t)SMEM_FLOATS * sizeof(float);
    cudaFuncSetAttribute(attn_fused_kernel,
                         cudaFuncAttributeMaxDynamicSharedMemorySize,
                         (int)smem_bytes);

    const int grid = B_ * H_ * (W_ / TW);   /* 2048 blocks */
    attn_fused_kernel<<<grid, 256, smem_bytes>>>(x, Wk, bk, Wq, bq, Wv, bv, Wo, bo, out);
}

// round 3
// speedup vs baseline: 1.8093x; 1.2277x over previous
#include <cuda_runtime.h>

typedef unsigned long long ull;

#define TW 4
#define C_ 64
#define D_ 32
#define S_ 32
#define SP_ 16
#define H_ 64
#define W_ 64
#define B_ 4
#define HW_ 4096
#define DHW_ 131072

#define XROW 68          /* x-tile: [w][d][c-contig], d-row stride */
#define PIXST 2184       /* 32*68 + 8 pad */
#define OROW 35          /* out-tile: [c][w][d], scalar conflict-light */
#define OFF_R1 0
#define N_R1 8960        /* max(4*2184=8736, 64*4*35=8960) */
#define KT_ROW 36        /* kT[i][s], 16B-aligned rows */
#define VS_ROW 68        /* vS[sp][2i] interleaved s-pairs */
#define N_PW (D_*KT_ROW + SP_*VS_ROW)   /* 1152 + 1088 = 2240 */
#define OFF_SC N_R1
#define SMEM_FLOATS (OFF_SC + 4*N_PW)   /* 17920 floats = 71680 B */

__constant__ float cWK[S_*C_];
__constant__ float cWQ[S_*C_];
__constant__ float cWV[S_*C_];
__constant__ float cWO[C_*S_];
__constant__ float cBK[S_];
__constant__ float cBQ[S_];
__constant__ float cBV[S_];
__constant__ float cBO[C_];

__device__ __forceinline__ ull f2fma(ull a, ull b, ull c) {
    ull d; asm("fma.rn.f32x2 %0,%1,%2,%3;" : "=l"(d) : "l"(a), "l"(b), "l"(c)); return d;
}
__device__ __forceinline__ ull f2add(ull a, ull b) {
    ull d; asm("add.rn.f32x2 %0,%1,%2;" : "=l"(d) : "l"(a), "l"(b)); return d;
}
__device__ __forceinline__ ull f2dup(float x) {
    ull d; asm("mov.b64 %0,{%1,%1};" : "=l"(d) : "f"(x)); return d;
}
__device__ __forceinline__ ull f2pack(float x, float y) {
    ull d; asm("mov.b64 %0,{%1,%2};" : "=l"(d) : "f"(x), "f"(y)); return d;
}
__device__ __forceinline__ float2 f2unpack(ull a) {
    float lo, hi; asm("mov.b64 {%0,%1},%2;" : "=f"(lo), "=f"(hi) : "l"(a));
    return make_float2(lo, hi);
}

/* one projection output channel s: dot(W[s,:], x) + b[s], c-pair packed */
#define PROJ_S(CW, CB, sIdx, val) {                                          \
    ull pa0=0ULL, pa1=0ULL, pa2=0ULL, pa3=0ULL;                              \
    _Pragma("unroll")                                                        \
    for (int t = 0; t < 16; t += 2) {                                        \
        const ulonglong2 wA = *(const ulonglong2*)&CW[(sIdx)*C_ + 4*t];      \
        pa0 = f2fma(wA.x, x2[2*t],   pa0);                                   \
        pa1 = f2fma(wA.y, x2[2*t+1], pa1);                                   \
        const ulonglong2 wB = *(const ulonglong2*)&CW[(sIdx)*C_ + 4*t + 4];  \
        pa2 = f2fma(wB.x, x2[2*t+2], pa2);                                   \
        pa3 = f2fma(wB.y, x2[2*t+3], pa3);                                   \
    }                                                                        \
    const float2 pp = f2unpack(f2add(f2add(pa0,pa2), f2add(pa1,pa3)));       \
    val = pp.x + pp.y + CB[sIdx];                                            \
}

__global__ void __launch_bounds__(128, 3)
attn_fused_kernel(const float* __restrict__ x, float* __restrict__ out)
{
    extern __shared__ float sm[];
    const int tid = threadIdx.x;
    const int bx  = blockIdx.x;
    const int wt  = bx & 15;
    const int h   = (bx >> 4) & 63;
    const int b   = bx >> 10;
    const int w0  = wt * TW;
    const int xbase = b*C_*DHW_ + h*W_ + w0;

    /* ---- stage x tile: [w][d][c-contig] ---- */
    for (int e = tid; e < C_*D_*TW; e += 128) {
        const int w = e & 3;
        const int d = (e >> 2) & 31;
        const int c = e >> 7;
        sm[OFF_R1 + w*PIXST + d*XROW + c] = x[xbase + c*DHW_ + d*HW_ + w];
    }
    __syncthreads();

    const int warp = tid >> 5;    /* pixel */
    const int lane = tid & 31;    /* d (and j) */

    /* ---- x fully into registers (16 LDS.128, conflict-free) ---- */
    ull x2[32];
    {
        const float* xr = sm + OFF_R1 + warp*PIXST + lane*XROW;
#pragma unroll
        for (int t = 0; t < 16; t++) {
            const ulonglong2 v = *(const ulonglong2*)&xr[4*t];
            x2[2*t] = v.x; x2[2*t+1] = v.y;
        }
    }
    __syncthreads();   /* x-tile region now dead -> reuse as out-tile */

    /* ---- pre-write residual into out-tile [c][w][d] ---- */
    float* otile = sm + OFF_R1;
#pragma unroll
    for (int cp = 0; cp < 32; cp++) {
        const float2 p = f2unpack(x2[cp]);
        otile[((2*cp  )*TW + warp)*OROW + lane] = p.x;
        otile[((2*cp+1)*TW + warp)*OROW + lane] = p.y;
    }

    float* kT = sm + OFF_SC + warp*N_PW;   /* kT[i][s], stride KT_ROW */
    float* vS = kT + D_*KT_ROW;            /* vS[sp][2i], stride VS_ROW */

    /* ---- K pass: compute k[s], store kT[i=lane][s] as s-pairs ---- */
#pragma unroll 4
    for (int sp = 0; sp < SP_; sp++) {
        float v0, v1;
        PROJ_S(cWK, cBK, 2*sp,   v0);
        PROJ_S(cWK, cBK, 2*sp+1, v1);
        *(ull*)&kT[lane*KT_ROW + 2*sp] = f2pack(v0, v1);
    }

    /* ---- Q pass: keep q packed s-pairs in registers ---- */
    ull q2[SP_];
#pragma unroll
    for (int sp = 0; sp < SP_; sp++) {
        float v0, v1;
        PROJ_S(cWQ, cBQ, 2*sp,   v0);
        PROJ_S(cWQ, cBQ, 2*sp+1, v1);
        q2[sp] = f2pack(v0, v1);
    }

    /* ---- V pass: store vS[sp][2*lane] ---- */
#pragma unroll 4
    for (int sp = 0; sp < SP_; sp++) {
        float v0, v1;
        PROJ_S(cWV, cBV, 2*sp,   v0);
        PROJ_S(cWV, cBV, 2*sp+1, v1);
        *(ull*)&vS[sp*VS_ROW + 2*lane] = f2pack(v0, v1);
    }
    __syncwarp();

    /* ---- scores[i][j=lane] = (1/sqrt(S)) sum_s k[s][i] q[s][j] ---- */
    float a[D_];
#pragma unroll
    for (int i = 0; i < D_; i++) {
        ull a0 = 0ULL, a1 = 0ULL;
#pragma unroll
        for (int t = 0; t < 8; t++) {
            const ulonglong2 kk = *(const ulonglong2*)&kT[i*KT_ROW + 4*t];
            a0 = f2fma(kk.x, q2[2*t],   a0);
            a1 = f2fma(kk.y, q2[2*t+1], a1);
        }
        const float2 p = f2unpack(f2add(a0, a1));
        a[i] = (p.x + p.y) * 0.17677669529663687f;
    }

    /* ---- softmax over i ---- */
    float m = a[0];
#pragma unroll
    for (int i = 1; i < D_; i++) m = fmaxf(m, a[i]);
    float ssum = 0.f;
#pragma unroll
    for (int i = 0; i < D_; i++) { a[i] = __expf(a[i] - m); ssum += a[i]; }
    const float inv = 1.0f / ssum;

    ull ad[D_];
#pragma unroll
    for (int i = 0; i < D_; i++) ad[i] = f2dup(a[i] * inv);

    /* ---- o[sp][j=lane] = sum_i v[s][i] a[i] (s-pair packed) ---- */
    ull o2[SP_];
#pragma unroll
    for (int sp = 0; sp < SP_; sp++) {
        ull a0 = 0ULL, a1 = 0ULL;
#pragma unroll
        for (int t = 0; t < 16; t++) {
            const ulonglong2 vv = *(const ulonglong2*)&vS[sp*VS_ROW + 4*t];
            a0 = f2fma(vv.x, ad[2*t],   a0);
            a1 = f2fma(vv.y, ad[2*t+1], a1);
        }
        o2[sp] = f2add(a0, a1);
    }

    /* ---- out[c] += Wo[c,:]·o + bo (residual already in otile) ---- */
#pragma unroll 8
    for (int c = 0; c < C_; c++) {
        ull a0 = 0ULL, a1 = 0ULL;
#pragma unroll
        for (int t = 0; t < 8; t++) {
            const ulonglong2 ww = *(const ulonglong2*)&cWO[c*S_ + 4*t];
            a0 = f2fma(ww.x, o2[2*t],   a0);
            a1 = f2fma(ww.y, o2[2*t+1], a1);
        }
        const float2 p = f2unpack(f2add(a0, a1));
        otile[(c*TW + warp)*OROW + lane] += p.x + p.y + cBO[c];
    }
    __syncthreads();

    /* ---- coalesced store ---- */
    for (int e = tid; e < C_*D_*TW; e += 128) {
        const int w = e & 3;
        const int d = (e >> 2) & 31;
        const int c = e >> 7;
        out[xbase + c*DHW_ + d*HW_ + w] = sm[OFF_R1 + (c*TW + w)*OROW + d];
    }
}

extern "C" void kernel_launch(void* const* d_in, const int* in_sizes, int n_in,
                              void* d_out, int out_size)
{
    const float* x = (const float*)d_in[0];
    float* out = (float*)d_out;

    /* weights/biases -> constant memory (D2D async, graph-capturable) */
    cudaMemcpyToSymbolAsync(cWK, d_in[1], S_*C_*sizeof(float), 0, cudaMemcpyDeviceToDevice, 0);
    cudaMemcpyToSymbolAsync(cBK, d_in[2], S_*sizeof(float),    0, cudaMemcpyDeviceToDevice, 0);
    cudaMemcpyToSymbolAsync(cWQ, d_in[3], S_*C_*sizeof(float), 0, cudaMemcpyDeviceToDevice, 0);
    cudaMemcpyToSymbolAsync(cBQ, d_in[4], S_*sizeof(float),    0, cudaMemcpyDeviceToDevice, 0);
    cudaMemcpyToSymbolAsync(cWV, d_in[5], S_*C_*sizeof(float), 0, cudaMemcpyDeviceToDevice, 0);
    cudaMemcpyToSymbolAsync(cBV, d_in[6], S_*sizeof(float),    0, cudaMemcpyDeviceToDevice, 0);
    cudaMemcpyToSymbolAsync(cWO, d_in[7], C_*S_*sizeof(float), 0, cudaMemcpyDeviceToDevice, 0);
    cudaMemcpyToSymbolAsync(cBO, d_in[8], C_*sizeof(float),    0, cudaMemcpyDeviceToDevice, 0);

    const size_t smem_bytes = (size_t)SMEM_FLOATS * sizeof(float);
    cudaFuncSetAttribute(attn_fused_kernel,
                         cudaFuncAttributeMaxDynamicSharedMemorySize,
                         (int)smem_bytes);

    const int grid = B_ * H_ * (W_ / TW);   /* 4096 blocks */
    attn_fused_kernel<<<grid, 128, smem_bytes>>>(x, out);
}